// round 2
// baseline (speedup 1.0000x reference)
#include <cuda_runtime.h>
#include <math_constants.h>

#define NNK      16
#define THREADS  128
#define GSZ      64
#define NMAX     8192
#define NGMAX    (NMAX / GSZ)

// ---------------- global scratch (static device memory: allowed) ------------
__device__ double g_sum_minrow;
__device__ double g_sum_mincol;
__device__ double g_sum_dens;

// sorted clouds as float4(x,y,z,|p|^2): [cloud 0=pred,1=true][batch][i]
__device__ float4 g_pts [2][2][NMAX];
__device__ float4 g_bmin[2][2][NGMAX];
__device__ float4 g_bmax[2][2][NGMAX];

__global__ void init_kernel() {
    g_sum_minrow = 0.0;
    g_sum_mincol = 0.0;
    g_sum_dens   = 0.0;
}

// ---------------- Morton helpers -------------------------------------------
__device__ __forceinline__ unsigned quant6(float v) {
    int q = (int)((v + 8.0f) * 4.0f);       // [-8,8] -> [0,64)
    q = q < 0 ? 0 : (q > 63 ? 63 : q);
    return (unsigned)q;
}
__device__ __forceinline__ unsigned spread3(unsigned v) {
    unsigned r = 0;
#pragma unroll
    for (int b = 0; b < 6; b++) r |= ((v >> b) & 1u) << (3 * b);
    return r;
}

// ---------------- sort kernel: one CTA per (cloud, batch) -------------------
__global__ void __launch_bounds__(1024)
sort_kernel(const float* __restrict__ y_pred, const float* __restrict__ y_true, int N) {
    __shared__ unsigned sk[NMAX];           // key = morton18 << 13 | idx13
    int cloud = blockIdx.x >> 1;
    int batch = blockIdx.x & 1;
    const float* src = (cloud ? y_true : y_pred) + (size_t)batch * N * 3;
    int tid = threadIdx.x;

    for (int i = tid; i < NMAX; i += 1024) {
        unsigned key = 0xFFFFFFFFu;
        if (i < N) {
            float x = src[3 * i], y = src[3 * i + 1], z = src[3 * i + 2];
            unsigned code = (spread3(quant6(x)) << 2) | (spread3(quant6(y)) << 1)
                          |  spread3(quant6(z));
            key = (code << 13) | (unsigned)i;
        }
        sk[i] = key;
    }
    __syncthreads();

    // bitonic sort ascending
    for (int k = 2; k <= NMAX; k <<= 1) {
        for (int j = k >> 1; j > 0; j >>= 1) {
            for (int i = tid; i < NMAX; i += 1024) {
                int ixj = i ^ j;
                if (ixj > i) {
                    unsigned a = sk[i], b = sk[ixj];
                    bool up = ((i & k) == 0);
                    if ((a > b) == up) { sk[i] = b; sk[ixj] = a; }
                }
            }
            __syncthreads();
        }
    }

    // gather sorted points
    for (int i = tid; i < N; i += 1024) {
        unsigned idx = sk[i] & 8191u;
        float x = src[3 * idx], y = src[3 * idx + 1], z = src[3 * idx + 2];
        g_pts[cloud][batch][i] = make_float4(x, y, z, x * x + y * y + z * z);
    }
    __syncthreads();

    // per-group bboxes
    int NG = N / GSZ;
    for (int g = tid; g < NG; g += 1024) {
        float mnx = CUDART_INF_F, mny = CUDART_INF_F, mnz = CUDART_INF_F;
        float mxx = -CUDART_INF_F, mxy = -CUDART_INF_F, mxz = -CUDART_INF_F;
        for (int t = 0; t < GSZ; t++) {
            float4 p = g_pts[cloud][batch][g * GSZ + t];
            mnx = fminf(mnx, p.x); mxx = fmaxf(mxx, p.x);
            mny = fminf(mny, p.y); mxy = fmaxf(mxy, p.y);
            mnz = fminf(mnz, p.z); mxz = fmaxf(mxz, p.z);
        }
        g_bmin[cloud][batch][g] = make_float4(mnx, mny, mnz, 0.f);
        g_bmax[cloud][batch][g] = make_float4(mxx, mxy, mxz, 0.f);
    }
}

// ---------------- top-k machinery ------------------------------------------
__device__ __forceinline__ void topk_insert(float (&knn)[NNK], float d2) {
    float x = d2;
#pragma unroll
    for (int k = 0; k < NNK; k++) {
        float lo = fminf(knn[k], x);
        x        = fmaxf(knn[k], x);
        knn[k]   = lo;
    }
}

// scan one sorted cloud maintaining top-NNK squared distances, with
// seeded start + warp-uniform group bbox pruning.
__device__ __forceinline__ void scan_topk(
    const float4* __restrict__ pts,
    const float4* __restrict__ bmin, const float4* __restrict__ bmax,
    int NG, int gseed,
    float qx, float qy, float qz, float x2,
    float qmnx, float qmny, float qmnz, float qmxx, float qmxy, float qmxz,
    float (&knn)[NNK])
{
    float kmax = CUDART_INF_F;
    int gs0 = max(0, gseed - 1), gs1 = min(NG - 1, gseed + 1);

    // seed: fill top-k from the query's own neighborhood
    for (int g = gs0; g <= gs1; g++) {
        int base = g * GSZ;
#pragma unroll 4
        for (int j = 0; j < GSZ; j++) {
            float4 s  = pts[base + j];
            float  d2 = fmaf(qx, s.x, fmaf(qy, s.y, fmaf(qz, s.z, x2 + s.w)));
            if (d2 < kmax) { topk_insert(knn, d2); kmax = knn[NNK - 1]; }
        }
    }

    // pruned full pass
    for (int g = 0; g < NG; g++) {
        if (g >= gs0 && g <= gs1) continue;
        float wk = kmax;
#pragma unroll
        for (int o = 16; o > 0; o >>= 1)
            wk = fmaxf(wk, __shfl_xor_sync(0xffffffffu, wk, o));
        float4 bn = bmin[g], bx = bmax[g];
        float dx = fmaxf(0.f, fmaxf(bn.x - qmxx, qmnx - bx.x));
        float dy = fmaxf(0.f, fmaxf(bn.y - qmxy, qmny - bx.y));
        float dz = fmaxf(0.f, fmaxf(bn.z - qmxz, qmnz - bx.z));
        float dmin2 = dx * dx + dy * dy + dz * dz;
        if (dmin2 > wk + 1e-3f) continue;            // conservative prune
        int base = g * GSZ;
#pragma unroll 4
        for (int j = 0; j < GSZ; j++) {
            float4 s  = pts[base + j];
            float  d2 = fmaf(qx, s.x, fmaf(qy, s.y, fmaf(qz, s.z, x2 + s.w)));
            if (d2 < kmax) { topk_insert(knn, d2); kmax = knn[NNK - 1]; }
        }
    }
}

// ---------------- kernel A: per TRUE point: knn to pred + knn to true -------
__global__ void __launch_bounds__(THREADS)
knn_kernel(int N) {
    __shared__ float redA[THREADS / 32];
    __shared__ float redB[THREADS / 32];

    int batch = blockIdx.y;
    int i = blockIdx.x * THREADS + threadIdx.x;

    float4 q  = g_pts[1][batch][i];
    float px = q.x, py = q.y, pz = q.z, x2 = q.w;
    float qx = -2.f * px, qy = -2.f * py, qz = -2.f * pz;

    // warp query bbox
    float qmnx = px, qmxx = px, qmny = py, qmxy = py, qmnz = pz, qmxz = pz;
#pragma unroll
    for (int o = 16; o > 0; o >>= 1) {
        qmnx = fminf(qmnx, __shfl_xor_sync(0xffffffffu, qmnx, o));
        qmxx = fmaxf(qmxx, __shfl_xor_sync(0xffffffffu, qmxx, o));
        qmny = fminf(qmny, __shfl_xor_sync(0xffffffffu, qmny, o));
        qmxy = fmaxf(qmxy, __shfl_xor_sync(0xffffffffu, qmxy, o));
        qmnz = fminf(qmnz, __shfl_xor_sync(0xffffffffu, qmnz, o));
        qmxz = fmaxf(qmxz, __shfl_xor_sync(0xffffffffu, qmxz, o));
    }

    int NG = N / GSZ;
    int gseed = i / GSZ;

    float knnp[NNK], knnt[NNK];
#pragma unroll
    for (int k = 0; k < NNK; k++) { knnp[k] = CUDART_INF_F; knnt[k] = CUDART_INF_F; }

    scan_topk(g_pts[0][batch], g_bmin[0][batch], g_bmax[0][batch], NG, gseed,
              qx, qy, qz, x2, qmnx, qmny, qmnz, qmxx, qmxy, qmxz, knnp);
    scan_topk(g_pts[1][batch], g_bmin[1][batch], g_bmax[1][batch], NG, gseed,
              qx, qy, qz, x2, qmnx, qmny, qmnz, qmxx, qmxy, qmxz, knnt);

    float minr = sqrtf(fmaxf(knnp[0], 0.f));
    float dens = 0.f;
#pragma unroll
    for (int k = 0; k < NNK; k++) {
        float dp = sqrtf(fmaxf(knnp[k], 0.f));
        float dt = sqrtf(fmaxf(knnt[k], 0.f));
        dens += fabsf(dp - dt);
    }

#pragma unroll
    for (int o = 16; o > 0; o >>= 1) {
        minr += __shfl_down_sync(0xffffffffu, minr, o);
        dens += __shfl_down_sync(0xffffffffu, dens, o);
    }
    if ((threadIdx.x & 31) == 0) {
        redA[threadIdx.x >> 5] = minr;
        redB[threadIdx.x >> 5] = dens;
    }
    __syncthreads();
    if (threadIdx.x == 0) {
        float a = 0.f, c = 0.f;
#pragma unroll
        for (int w = 0; w < THREADS / 32; w++) { a += redA[w]; c += redB[w]; }
        atomicAdd(&g_sum_minrow, (double)a);
        atomicAdd(&g_sum_dens,   (double)c);
    }
}

// ---------------- kernel B: per PRED point: min dist to true ----------------
__global__ void __launch_bounds__(THREADS)
mincol_kernel(int N) {
    __shared__ float redA[THREADS / 32];

    int batch = blockIdx.y;
    int j = blockIdx.x * THREADS + threadIdx.x;

    float4 q  = g_pts[0][batch][j];
    float px = q.x, py = q.y, pz = q.z, x2 = q.w;
    float qx = -2.f * px, qy = -2.f * py, qz = -2.f * pz;

    float qmnx = px, qmxx = px, qmny = py, qmxy = py, qmnz = pz, qmxz = pz;
#pragma unroll
    for (int o = 16; o > 0; o >>= 1) {
        qmnx = fminf(qmnx, __shfl_xor_sync(0xffffffffu, qmnx, o));
        qmxx = fmaxf(qmxx, __shfl_xor_sync(0xffffffffu, qmxx, o));
        qmny = fminf(qmny, __shfl_xor_sync(0xffffffffu, qmny, o));
        qmxy = fmaxf(qmxy, __shfl_xor_sync(0xffffffffu, qmxy, o));
        qmnz = fminf(qmnz, __shfl_xor_sync(0xffffffffu, qmnz, o));
        qmxz = fmaxf(qmxz, __shfl_xor_sync(0xffffffffu, qmxz, o));
    }

    const float4* pts  = g_pts [1][batch];
    const float4* bmin = g_bmin[1][batch];
    const float4* bmax = g_bmax[1][batch];
    int NG = N / GSZ;
    int gseed = j / GSZ;
    int gs0 = max(0, gseed - 1), gs1 = min(NG - 1, gseed + 1);

    float m = CUDART_INF_F;
    for (int g = gs0; g <= gs1; g++) {
        int base = g * GSZ;
#pragma unroll 8
        for (int t = 0; t < GSZ; t++) {
            float4 s  = pts[base + t];
            float  d2 = fmaf(qx, s.x, fmaf(qy, s.y, fmaf(qz, s.z, x2 + s.w)));
            m = fminf(m, d2);
        }
    }
    for (int g = 0; g < NG; g++) {
        if (g >= gs0 && g <= gs1) continue;
        float wm = m;
#pragma unroll
        for (int o = 16; o > 0; o >>= 1)
            wm = fmaxf(wm, __shfl_xor_sync(0xffffffffu, wm, o));
        float4 bn = bmin[g], bx = bmax[g];
        float dx = fmaxf(0.f, fmaxf(bn.x - qmxx, qmnx - bx.x));
        float dy = fmaxf(0.f, fmaxf(bn.y - qmxy, qmny - bx.y));
        float dz = fmaxf(0.f, fmaxf(bn.z - qmxz, qmnz - bx.z));
        float dmin2 = dx * dx + dy * dy + dz * dz;
        if (dmin2 > wm + 1e-3f) continue;
        int base = g * GSZ;
#pragma unroll 8
        for (int t = 0; t < GSZ; t++) {
            float4 s  = pts[base + t];
            float  d2 = fmaf(qx, s.x, fmaf(qy, s.y, fmaf(qz, s.z, x2 + s.w)));
            m = fminf(m, d2);
        }
    }

    float mc = sqrtf(fmaxf(m, 0.f));
#pragma unroll
    for (int o = 16; o > 0; o >>= 1) mc += __shfl_down_sync(0xffffffffu, mc, o);
    if ((threadIdx.x & 31) == 0) redA[threadIdx.x >> 5] = mc;
    __syncthreads();
    if (threadIdx.x == 0) {
        float a = 0.f;
#pragma unroll
        for (int w = 0; w < THREADS / 32; w++) a += redA[w];
        atomicAdd(&g_sum_mincol, (double)a);
    }
}

__global__ void finalize_kernel(float* __restrict__ out, int BN) {
    double inv   = 1.0 / (double)BN;
    double shape = 0.5 * (g_sum_minrow * inv + g_sum_mincol * inv);
    double dens  = g_sum_dens / ((double)BN * (double)NNK);
    out[0] = (float)(shape + dens);
    out[1] = (float)shape;
    out[2] = (float)dens;
}

extern "C" void kernel_launch(void* const* d_in, const int* in_sizes, int n_in,
                              void* d_out, int out_size) {
    const float* y_pred = (const float*)d_in[0];
    const float* y_true = (const float*)d_in[1];
    const int B = 2, C = 3;
    int N = in_sizes[0] / (B * C);

    init_kernel<<<1, 1>>>();
    sort_kernel<<<4, 1024>>>(y_pred, y_true, N);
    dim3 grid(N / THREADS, B);
    knn_kernel<<<grid, THREADS>>>(N);
    mincol_kernel<<<grid, THREADS>>>(N);
    finalize_kernel<<<1, 1>>>((float*)d_out, B * N);
}

// round 3
// speedup vs baseline: 2.6940x; 2.6940x over previous
#include <cuda_runtime.h>
#include <math_constants.h>

#define NNK      16
#define THREADS  256
#define GSZ      32
#define NMAX     8192
#define NGMAX    (NMAX / GSZ)
#define PRUNE_EPS 1e-4f

// ---------------- global scratch (static device memory: allowed) ------------
__device__ double g_sum_minrow;
__device__ double g_sum_mincol;
__device__ double g_sum_dens;

// sorted clouds as float4(x,y,z,|p|^2): [cloud 0=pred,1=true][batch][i]
__device__ float4 g_pts [2][2][NMAX];
__device__ float4 g_bmin[2][2][NGMAX];
__device__ float4 g_bmax[2][2][NGMAX];

__global__ void init_kernel() {
    g_sum_minrow = 0.0;
    g_sum_mincol = 0.0;
    g_sum_dens   = 0.0;
}

// ---------------- Morton helpers -------------------------------------------
__device__ __forceinline__ unsigned quant6(float v) {
    int q = (int)((v + 8.0f) * 4.0f);       // [-8,8] -> [0,64)
    q = q < 0 ? 0 : (q > 63 ? 63 : q);
    return (unsigned)q;
}
__device__ __forceinline__ unsigned spread3(unsigned v) {
    unsigned r = 0;
#pragma unroll
    for (int b = 0; b < 6; b++) r |= ((v >> b) & 1u) << (3 * b);
    return r;
}

// ---------------- sort kernel: one CTA per (cloud, batch) -------------------
__global__ void __launch_bounds__(1024)
sort_kernel(const float* __restrict__ y_pred, const float* __restrict__ y_true, int N) {
    __shared__ unsigned sk[NMAX];           // key = morton18 << 13 | idx13
    int cloud = blockIdx.x >> 1;
    int batch = blockIdx.x & 1;
    const float* src = (cloud ? y_true : y_pred) + (size_t)batch * N * 3;
    int tid = threadIdx.x;

    for (int i = tid; i < NMAX; i += 1024) {
        unsigned key = 0xFFFFFFFFu;
        if (i < N) {
            float x = src[3 * i], y = src[3 * i + 1], z = src[3 * i + 2];
            unsigned code = (spread3(quant6(x)) << 2) | (spread3(quant6(y)) << 1)
                          |  spread3(quant6(z));
            key = (code << 13) | (unsigned)i;
        }
        sk[i] = key;
    }
    __syncthreads();

    // bitonic sort ascending
    for (int k = 2; k <= NMAX; k <<= 1) {
        for (int j = k >> 1; j > 0; j >>= 1) {
            for (int i = tid; i < NMAX; i += 1024) {
                int ixj = i ^ j;
                if (ixj > i) {
                    unsigned a = sk[i], b = sk[ixj];
                    bool up = ((i & k) == 0);
                    if ((a > b) == up) { sk[i] = b; sk[ixj] = a; }
                }
            }
            __syncthreads();
        }
    }

    // gather sorted points
    for (int i = tid; i < N; i += 1024) {
        unsigned idx = sk[i] & 8191u;
        float x = src[3 * idx], y = src[3 * idx + 1], z = src[3 * idx + 2];
        g_pts[cloud][batch][i] = make_float4(x, y, z, x * x + y * y + z * z);
    }
    __syncthreads();

    // per-group bboxes
    int NG = N / GSZ;
    for (int g = tid; g < NG; g += 1024) {
        float mnx = CUDART_INF_F, mny = CUDART_INF_F, mnz = CUDART_INF_F;
        float mxx = -CUDART_INF_F, mxy = -CUDART_INF_F, mxz = -CUDART_INF_F;
        for (int t = 0; t < GSZ; t++) {
            float4 p = g_pts[cloud][batch][g * GSZ + t];
            mnx = fminf(mnx, p.x); mxx = fmaxf(mxx, p.x);
            mny = fminf(mny, p.y); mxy = fmaxf(mxy, p.y);
            mnz = fminf(mnz, p.z); mxz = fmaxf(mxz, p.z);
        }
        g_bmin[cloud][batch][g] = make_float4(mnx, mny, mnz, 0.f);
        g_bmax[cloud][batch][g] = make_float4(mxx, mxy, mxz, 0.f);
    }
}

// ---------------- top-k machinery ------------------------------------------
__device__ __forceinline__ void topk_insert(float (&knn)[NNK], float d2) {
    float x = d2;
#pragma unroll
    for (int k = 0; k < NNK; k++) {
        float lo = fminf(knn[k], x);
        x        = fmaxf(knn[k], x);
        knn[k]   = lo;
    }
}

// scan one group of GSZ points, maintaining per-lane top-k.
__device__ __forceinline__ void scan_group(const float4* __restrict__ pts, int base,
                                           float qx, float qy, float qz, float x2,
                                           float (&knn)[NNK], float& kmax) {
#pragma unroll 8
    for (int j = 0; j < GSZ; j++) {
        float4 s  = pts[base + j];
        float  d2 = fmaf(qx, s.x, fmaf(qy, s.y, fmaf(qz, s.z, x2 + s.w)));
        if (d2 < kmax) { topk_insert(knn, d2); kmax = knn[NNK - 1]; }
    }
}

// full scan with seed + per-lane bbox prune (bboxes staged in shared).
__device__ __forceinline__ void scan_topk(
    const float4* __restrict__ pts,
    const float4* __restrict__ sbmin, const float4* __restrict__ sbmax,
    int NG, int gseed,
    float px, float py, float pz,
    float qx, float qy, float qz, float x2,
    float (&knn)[NNK])
{
    float kmax = CUDART_INF_F;
    int gs0 = max(0, gseed - 1), gs1 = min(NG - 1, gseed + 1);

    for (int g = gs0; g <= gs1; g++)
        scan_group(pts, g * GSZ, qx, qy, qz, x2, knn, kmax);

    for (int g = 0; g < NG; g++) {
        if (g >= gs0 && g <= gs1) continue;
        float4 bn = sbmin[g], bx = sbmax[g];
        float dx = fmaxf(0.f, fmaxf(bn.x - px, px - bx.x));
        float dy = fmaxf(0.f, fmaxf(bn.y - py, py - bx.y));
        float dz = fmaxf(0.f, fmaxf(bn.z - pz, pz - bx.z));
        float dmin2 = fmaf(dx, dx, fmaf(dy, dy, dz * dz));
        bool  act   = dmin2 <= kmax + PRUNE_EPS;
        if (__any_sync(0xffffffffu, act))
            scan_group(pts, g * GSZ, qx, qy, qz, x2, knn, kmax);
    }
}

// ---------------- kernel A: per TRUE point: knn to pred + knn to true -------
__global__ void __launch_bounds__(THREADS)
knn_kernel(int N) {
    __shared__ float4 sbminP[NGMAX], sbmaxP[NGMAX];
    __shared__ float4 sbminT[NGMAX], sbmaxT[NGMAX];
    __shared__ float  redA[THREADS / 32];
    __shared__ float  redB[THREADS / 32];

    int batch = blockIdx.y;
    int i = blockIdx.x * THREADS + threadIdx.x;
    int NG = N / GSZ;

    for (int g = threadIdx.x; g < NG; g += THREADS) {
        sbminP[g] = g_bmin[0][batch][g];
        sbmaxP[g] = g_bmax[0][batch][g];
        sbminT[g] = g_bmin[1][batch][g];
        sbmaxT[g] = g_bmax[1][batch][g];
    }
    __syncthreads();

    float4 q  = g_pts[1][batch][i];
    float px = q.x, py = q.y, pz = q.z, x2 = q.w;
    float qx = -2.f * px, qy = -2.f * py, qz = -2.f * pz;

    int gseed = i / GSZ;

    float knnp[NNK], knnt[NNK];
#pragma unroll
    for (int k = 0; k < NNK; k++) { knnp[k] = CUDART_INF_F; knnt[k] = CUDART_INF_F; }

    scan_topk(g_pts[0][batch], sbminP, sbmaxP, NG, gseed,
              px, py, pz, qx, qy, qz, x2, knnp);
    scan_topk(g_pts[1][batch], sbminT, sbmaxT, NG, gseed,
              px, py, pz, qx, qy, qz, x2, knnt);

    float minr = sqrtf(fmaxf(knnp[0], 0.f));
    float dens = 0.f;
#pragma unroll
    for (int k = 0; k < NNK; k++) {
        float dp = sqrtf(fmaxf(knnp[k], 0.f));
        float dt = sqrtf(fmaxf(knnt[k], 0.f));
        dens += fabsf(dp - dt);
    }

#pragma unroll
    for (int o = 16; o > 0; o >>= 1) {
        minr += __shfl_down_sync(0xffffffffu, minr, o);
        dens += __shfl_down_sync(0xffffffffu, dens, o);
    }
    if ((threadIdx.x & 31) == 0) {
        redA[threadIdx.x >> 5] = minr;
        redB[threadIdx.x >> 5] = dens;
    }
    __syncthreads();
    if (threadIdx.x == 0) {
        float a = 0.f, c = 0.f;
#pragma unroll
        for (int w = 0; w < THREADS / 32; w++) { a += redA[w]; c += redB[w]; }
        atomicAdd(&g_sum_minrow, (double)a);
        atomicAdd(&g_sum_dens,   (double)c);
    }
}

// ---------------- kernel B: per PRED point: min dist to true ----------------
__global__ void __launch_bounds__(THREADS)
mincol_kernel(int N) {
    __shared__ float4 sbminT[NGMAX], sbmaxT[NGMAX];
    __shared__ float  redA[THREADS / 32];

    int batch = blockIdx.y;
    int j = blockIdx.x * THREADS + threadIdx.x;
    int NG = N / GSZ;

    for (int g = threadIdx.x; g < NG; g += THREADS) {
        sbminT[g] = g_bmin[1][batch][g];
        sbmaxT[g] = g_bmax[1][batch][g];
    }
    __syncthreads();

    float4 q  = g_pts[0][batch][j];
    float px = q.x, py = q.y, pz = q.z, x2 = q.w;
    float qx = -2.f * px, qy = -2.f * py, qz = -2.f * pz;

    const float4* pts = g_pts[1][batch];
    int gseed = j / GSZ;
    int gs0 = max(0, gseed - 1), gs1 = min(NG - 1, gseed + 1);

    float m = CUDART_INF_F;
    for (int g = gs0; g <= gs1; g++) {
        int base = g * GSZ;
#pragma unroll 8
        for (int t = 0; t < GSZ; t++) {
            float4 s  = pts[base + t];
            float  d2 = fmaf(qx, s.x, fmaf(qy, s.y, fmaf(qz, s.z, x2 + s.w)));
            m = fminf(m, d2);
        }
    }
    for (int g = 0; g < NG; g++) {
        if (g >= gs0 && g <= gs1) continue;
        float4 bn = sbminT[g], bx = sbmaxT[g];
        float dx = fmaxf(0.f, fmaxf(bn.x - px, px - bx.x));
        float dy = fmaxf(0.f, fmaxf(bn.y - py, py - bx.y));
        float dz = fmaxf(0.f, fmaxf(bn.z - pz, pz - bx.z));
        float dmin2 = fmaf(dx, dx, fmaf(dy, dy, dz * dz));
        bool  act   = dmin2 <= m + PRUNE_EPS;
        if (__any_sync(0xffffffffu, act)) {
            int base = g * GSZ;
#pragma unroll 8
            for (int t = 0; t < GSZ; t++) {
                float4 s  = pts[base + t];
                float  d2 = fmaf(qx, s.x, fmaf(qy, s.y, fmaf(qz, s.z, x2 + s.w)));
                m = fminf(m, d2);
            }
        }
    }

    float mc = sqrtf(fmaxf(m, 0.f));
#pragma unroll
    for (int o = 16; o > 0; o >>= 1) mc += __shfl_down_sync(0xffffffffu, mc, o);
    if ((threadIdx.x & 31) == 0) redA[threadIdx.x >> 5] = mc;
    __syncthreads();
    if (threadIdx.x == 0) {
        float a = 0.f;
#pragma unroll
        for (int w = 0; w < THREADS / 32; w++) a += redA[w];
        atomicAdd(&g_sum_mincol, (double)a);
    }
}

__global__ void finalize_kernel(float* __restrict__ out, int BN) {
    double inv   = 1.0 / (double)BN;
    double shape = 0.5 * (g_sum_minrow * inv + g_sum_mincol * inv);
    double dens  = g_sum_dens / ((double)BN * (double)NNK);
    out[0] = (float)(shape + dens);
    out[1] = (float)shape;
    out[2] = (float)dens;
}

extern "C" void kernel_launch(void* const* d_in, const int* in_sizes, int n_in,
                              void* d_out, int out_size) {
    const float* y_pred = (const float*)d_in[0];
    const float* y_true = (const float*)d_in[1];
    const int B = 2, C = 3;
    int N = in_sizes[0] / (B * C);

    init_kernel<<<1, 1>>>();
    sort_kernel<<<4, 1024>>>(y_pred, y_true, N);
    dim3 grid(N / THREADS, B);
    knn_kernel<<<grid, THREADS>>>(N);
    mincol_kernel<<<grid, THREADS>>>(N);
    finalize_kernel<<<1, 1>>>((float*)d_out, B * N);
}